// round 7
// baseline (speedup 1.0000x reference)
#include <cuda_runtime.h>

// Problem constants
#define BATCH     16
#define WIDTH     262144
#define FLEN      32
#define WOUT      (WIDTH - FLEN + 1)      // 262113
#define TPB       128
#define OPT       8                       // outputs per thread
#define TILE_OUT  (TPB * OPT)             // 1024
#define TILE_IN   (TILE_OUT + FLEN - 1)   // 1055
#define NTILES    ((WOUT + TILE_OUT - 1) / TILE_OUT)  // 256
#define SCALEF    0.1778279410038923f     // sqrt(10^-1.5)
#define CHUNKS    4
#define CT        (FLEN / CHUNKS)         // 8 taps per chunk
#define WIN       (CT + OPT - 1)          // 15-element sliding window

// Padded shared index at float2 (8B) granularity: base tid*8 -> lane stride
// 9 elems = 72B; bank = 18*l mod 32 distinct within each 16-lane LDS.64 phase
// -> conflict-free.
__device__ __forceinline__ int p2(int i) { return i + (i >> 3); }
#define SH_SZ (TILE_IN + (TILE_IN >> 3) + 8)   // ~1194 float2 = 9.6 KB

typedef unsigned long long ull;

// ---- packed f32x2 helpers (PTX-only; ptxas won't auto-fuse) ----
__device__ __forceinline__ ull pack2(float lo, float hi) {
    ull r;
    asm("mov.b64 %0, {%1,%2};" : "=l"(r) : "f"(lo), "f"(hi));
    return r;
}
__device__ __forceinline__ void unpack2(ull v, float& lo, float& hi) {
    asm("mov.b64 {%0,%1}, %2;" : "=f"(lo), "=f"(hi) : "l"(v));
}
__device__ __forceinline__ void ffma2(ull& c, ull a, ull b) {
    asm("fma.rn.f32x2 %0, %1, %2, %0;" : "+l"(c) : "l"(a), "l"(b));
}
__device__ __forceinline__ ull ld_sh2(const float2* p) {
    float2 v = *p;
    return pack2(v.x, v.y);
}

// Single-MUFU tanh (sm_75+).
__device__ __forceinline__ float tanh_mufu(float x) {
    float y;
    asm("tanh.approx.f32 %0, %1;" : "=f"(y) : "f"(x));
    return y;
}

__global__ __launch_bounds__(TPB, 8)
void hammer_wiener_kernel(
    const float* __restrict__ xr_g, const float* __restrict__ xi_g,
    const float* __restrict__ w1pre_g, const float* __restrict__ w2pre_g,
    const float* __restrict__ wfr_g,   const float* __restrict__ wfi_g,
    const float* __restrict__ w1po_g,  const float* __restrict__ b1po_g,
    const float* __restrict__ w2po_g,  const float* __restrict__ b2po_g,
    float2* __restrict__ out)
{
    __shared__ float2 shx[SH_SZ];                 // (xr, xi): 8B/elem
    __shared__ ull swr_p[FLEN], swi_p[FLEN];      // pre-packed (w,w) pairs
    __shared__ float sw1[8], sw2[8], sw1p[8], sb1p[8], sw2p[8];
    __shared__ float sb2;

    const int tid  = threadIdx.x;
    const int tile = blockIdx.x;
    const int b    = blockIdx.y;
    const int t0   = tile * TILE_OUT;

    // ---- stage weights into shared (FIR weights pre-packed as f32x2) ----
    if (tid < FLEN) {
        const float wr = wfr_g[tid];
        const float wi = wfi_g[tid];
        swr_p[tid] = pack2(wr, wr);
        swi_p[tid] = pack2(wi, wi);
    } else if (tid < FLEN + 8) {
        int f = tid - FLEN;
        sw1[f]  = w1pre_g[f];
        sw2[f]  = w2pre_g[f];
        sw1p[f] = w1po_g[f];
        sb1p[f] = b1po_g[f];
        sw2p[f] = w2po_g[f];
        if (f == 0) sb2 = b2po_g[0];
    }
    __syncthreads();

    // ---- pre-stage: |x| MLP (tanh) + rotation -> (xr,xi) into shared ----
    {
        const float* xr_row = xr_g + (size_t)b * WIDTH + t0;
        const float* xi_row = xi_g + (size_t)b * WIDTH + t0;
        float cw1[8], cw2[8];
        #pragma unroll
        for (int f = 0; f < 8; f++) { cw1[f] = sw1[f]; cw2[f] = sw2[f]; }

        // vector part: 1024 elems = 2 iters x 128 threads x float4 (tile base
        // is 4KB-aligned; in-bounds since t0+1023 <= WIDTH-1)
        #pragma unroll
        for (int it = 0; it < 2; it++) {
            const int i = (it * TPB + tid) * 4;
            const float4 vr = *reinterpret_cast<const float4*>(xr_row + i);
            const float4 vi = *reinterpret_cast<const float4*>(xi_row + i);
            const float rr[4] = {vr.x, vr.y, vr.z, vr.w};
            const float ii[4] = {vi.x, vi.y, vi.z, vi.w};
            #pragma unroll
            for (int k = 0; k < 4; k++) {
                const float xr = rr[k], xi = ii[k];
                float s   = fmaf(xr, xr, xi * xi);
                float inv = (s > 0.0f) ? rsqrtf(s) : 0.0f;
                float mag = s * inv;
                float m = 0.0f;
                #pragma unroll
                for (int f = 0; f < 8; f++)
                    m = fmaf(tanh_mufu(mag * cw1[f]), cw2[f], m);
                shx[p2(i + k)] = make_float2(m * (xr * inv), m * (xi * inv));
            }
        }
        // scalar halo: 31 elems, guard global bound (last tile overruns WIDTH)
        if (tid < TILE_IN - TILE_OUT) {
            const int i  = TILE_OUT + tid;
            const int gi = t0 + i;
            float xr = 0.0f, xi = 0.0f;
            if (gi < WIDTH) { xr = xr_row[i]; xi = xi_row[i]; }
            float s   = fmaf(xr, xr, xi * xi);
            float inv = (s > 0.0f) ? rsqrtf(s) : 0.0f;
            float mag = s * inv;
            float m = 0.0f;
            #pragma unroll
            for (int f = 0; f < 8; f++)
                m = fmaf(tanh_mufu(mag * cw1[f]), cw2[f], m);
            shx[p2(i)] = make_float2(m * (xr * inv), m * (xi * inv));
        }
    }
    __syncthreads();

    // ---- complex FIR: dual packed accumulators, tap-major sliding window ----
    // accA[o] = (Σ xr·wr, Σ xi·wr) ; accB[o] = (Σ xr·wi, Σ xi·wi)
    ull accA[OPT], accB[OPT];
    #pragma unroll
    for (int o = 0; o < OPT; o++) { accA[o] = 0ull; accB[o] = 0ull; }

    #pragma unroll 1
    for (int c = 0; c < CHUNKS; c++) {
        // element index i = 8*(tid+c) + j ; padded: 9*(tid+c) + j + (j>>3)
        const int bb = 9 * (tid + c);
        ull xw[WIN];
        // preload window [0..8] (covers k=0 plus 1-ahead prefetch)
        #pragma unroll
        for (int j = 0; j < OPT + 1; j++)
            xw[j] = ld_sh2(&shx[bb + j + (j >> 3)]);

        #pragma unroll
        for (int k = 0; k < CT; k++) {
            // prefetch x for iteration k+2 (uses up to index (k+2)+7)
            if (k + OPT + 1 < WIN) {
                const int j = k + OPT + 1;
                xw[j] = ld_sh2(&shx[bb + j + (j >> 3)]);
            }
            const ull wrr = swr_p[c * CT + k];   // LDS.64 broadcast
            const ull wii = swi_p[c * CT + k];
            #pragma unroll
            for (int o = 0; o < OPT; o++) {
                ffma2(accA[o], xw[k + o], wrr);
                ffma2(accB[o], xw[k + o], wii);
            }
        }
    }

    // ---- post-stage MLP (relu) + rotation + store ----
    float cw1p[8], cb1p[8], cw2p[8];
    #pragma unroll
    for (int f = 0; f < 8; f++) { cw1p[f] = sw1p[f]; cb1p[f] = sb1p[f]; cw2p[f] = sw2p[f]; }
    const float cb2 = sb2;

    const int obase = t0 + tid * OPT;
    float2* orow = out + (size_t)b * WOUT + obase;
    #pragma unroll
    for (int o = 0; o < OPT; o++) {
        if (obase + o < WOUT) {
            float alo, ahi, blo, bhi;
            unpack2(accA[o], alo, ahi);
            unpack2(accB[o], blo, bhi);
            const float zr = alo - bhi;   // Σ xr·wr − Σ xi·wi
            const float zi = ahi + blo;   // Σ xi·wr + Σ xr·wi
            float s    = fmaf(zr, zr, zi * zi);
            float inv  = (s > 0.0f) ? rsqrtf(s) : 0.0f;
            float zmag = s * inv;
            float cosz = (s > 0.0f) ? zr * inv : 1.0f;
            float sinz = zi * inv;
            float zm = cb2;
            #pragma unroll
            for (int f = 0; f < 8; f++) {
                float g = fmaf(zmag, cw1p[f], cb1p[f]);
                g = fmaxf(g, 0.0f);
                zm = fmaf(g, cw2p[f], zm);
            }
            const float cf = SCALEF * zm;
            orow[o] = make_float2(cf * cosz, cf * sinz);
        }
    }
}

extern "C" void kernel_launch(void* const* d_in, const int* in_sizes, int n_in,
                              void* d_out, int out_size)
{
    (void)in_sizes; (void)n_in; (void)out_size;
    const float* xr   = (const float*)d_in[0];
    const float* xi   = (const float*)d_in[1];
    const float* w1pr = (const float*)d_in[2];
    const float* w2pr = (const float*)d_in[3];
    const float* wfr  = (const float*)d_in[4];
    const float* wfi  = (const float*)d_in[5];
    const float* w1po = (const float*)d_in[6];
    const float* b1po = (const float*)d_in[7];
    const float* w2po = (const float*)d_in[8];
    const float* b2po = (const float*)d_in[9];

    dim3 grid(NTILES, BATCH);
    hammer_wiener_kernel<<<grid, TPB>>>(xr, xi, w1pr, w2pr, wfr, wfi,
                                        w1po, b1po, w2po, b2po,
                                        (float2*)d_out);
}